// round 8
// baseline (speedup 1.0000x reference)
#include <cuda_runtime.h>

#define NL 25
#define ED 64
#define HD 8
#define NB 1000
#define NS 512
#define CS 5          // CTAs (batch slices) per layer
#define BPC 200       // batch pairs per CTA
#define TPB 416       // 13 full warps; 400 active threads (200 pairs)

typedef unsigned long long u64;

// Scratch (static __device__ arrays; allocation-free per harness rules)
__device__ float g_xproj[NS * NB * 24];                    // layer-0 x-projections (+bias)
__device__ float g_hbuf[(NL - 1) * NS * NB * HD];          // inter-layer h buffers
__device__ unsigned int g_cnt[(NL - 1) * NB];              // per-(layer,b) progress counters

// ---------- f32x2 packed-FMA helpers ----------
__device__ __forceinline__ u64 pk2(float v) {
    u64 d; asm("mov.b64 %0,{%1,%1};" : "=l"(d) : "f"(v)); return d;
}
__device__ __forceinline__ u64 pkab(float a, float b) {
    u64 d; asm("mov.b64 %0,{%1,%2};" : "=l"(d) : "f"(a), "f"(b)); return d;
}
__device__ __forceinline__ void upk(u64 v, float& a, float& b) {
    asm("mov.b64 {%0,%1},%2;" : "=f"(a), "=f"(b) : "l"(v));
}
__device__ __forceinline__ u64 f2fma(u64 a, u64 b, u64 c) {
    u64 d; asm("fma.rn.f32x2 %0,%1,%2,%3;" : "=l"(d) : "l"(a), "l"(b), "l"(c)); return d;
}
// acc[0..1] (4 floats = own half-row) += s2 * wrow[hf*4 .. hf*4+3]  (1x LDS.128)
__device__ __forceinline__ void fma4w(u64* acc, u64 s2, const float* wrow_own) {
    ulonglong2 w = *(const ulonglong2*)(wrow_own);
    acc[0] = f2fma(s2, w.x, acc[0]); acc[1] = f2fma(s2, w.y, acc[1]);
}
// full-row version for precompute kernel
__device__ __forceinline__ void fma8w(u64* acc, u64 s2, const float* wrow) {
    ulonglong2 w01 = *(const ulonglong2*)(wrow);
    ulonglong2 w23 = *(const ulonglong2*)(wrow + 4);
    acc[0] = f2fma(s2, w01.x, acc[0]); acc[1] = f2fma(s2, w01.y, acc[1]);
    acc[2] = f2fma(s2, w23.x, acc[2]); acc[3] = f2fma(s2, w23.y, acc[3]);
}

// ---------- MUFU.TANH activations ----------
__device__ __forceinline__ float tanh_hw(float x) {
    float t; asm("tanh.approx.f32 %0,%1;" : "=f"(t) : "f"(x)); return t;
}
__device__ __forceinline__ float sigm(float x) {
    return fmaf(0.5f, tanh_hw(0.5f * x), 0.5f);
}

// ---------- precompute: layer-0 x-projections + counter clear ----------
__global__ void __launch_bounds__(256) precompute_xproj(
    const int* __restrict__ x, const float* __restrict__ emb,
    const float* __restrict__ Wxz0, const float* __restrict__ bz0,
    const float* __restrict__ Wxr0, const float* __restrict__ br0,
    const float* __restrict__ WxH0, const float* __restrict__ bH0)
{
    __shared__ __align__(16) float sw[3][ED][8];
    __shared__ __align__(16) float sb[24];
    const int tid = threadIdx.x;
    for (int i = tid; i < ED * HD; i += blockDim.x) {
        ((float*)sw[0])[i] = Wxz0[i];
        ((float*)sw[1])[i] = Wxr0[i];
        ((float*)sw[2])[i] = WxH0[i];
    }
    if (tid < 8) { sb[tid] = bz0[tid]; sb[8 + tid] = br0[tid]; sb[16 + tid] = bH0[tid]; }
    __syncthreads();

    const int gid = blockIdx.x * blockDim.x + tid;   // NB*NS = 512000 threads

    // clear counters: (NL-1)*NB = 24000 u32 = 6000 uint4
    if (gid < (NL - 1) * NB / 4) {
        ((uint4*)g_cnt)[gid] = make_uint4(0u, 0u, 0u, 0u);
    }

    if (gid >= NB * NS) return;
    const int b = gid / NS, t = gid % NS;
    const int idx = x[gid];
    const float4* e4 = (const float4*)(emb + (long long)idx * ED);

    const u64* sb2 = (const u64*)sb;
    u64 acc[12];
    #pragma unroll
    for (int j = 0; j < 12; j++) acc[j] = sb2[j];

    #pragma unroll
    for (int k4 = 0; k4 < ED / 4; k4++) {
        float4 ev = e4[k4];
        float es[4] = {ev.x, ev.y, ev.z, ev.w};
        #pragma unroll
        for (int q = 0; q < 4; q++) {
            const int k = k4 * 4 + q;
            const u64 s2 = pk2(es[q]);
            fma8w(acc,     s2, sw[0][k]);
            fma8w(acc + 4, s2, sw[1][k]);
            fma8w(acc + 8, s2, sw[2][k]);
        }
    }
    float o[24];
    #pragma unroll
    for (int j = 0; j < 12; j++) upk(acc[j], o[2 * j], o[2 * j + 1]);
    float4* o4 = (float4*)(g_xproj + ((long long)t * NB + b) * 24);
    #pragma unroll
    for (int j = 0; j < 6; j++)
        o4[j] = make_float4(o[4 * j], o[4 * j + 1], o[4 * j + 2], o[4 * j + 3]);
}

// ---------- persistent layer-pipelined GRU, 2 threads per batch ----------
// blockIdx = layer*CS + slice. Thread pair (b, hf): hf owns output columns
// hf*4..hf*4+3. Full h kept per-thread via shfl exchange; r exchanged mid-cell.
__global__ void __launch_bounds__(TPB, 1) gru_pipeline(
    const float* __restrict__ Whz0, const float* __restrict__ Whr0, const float* __restrict__ WrH0,
    const float* __restrict__ Wxz, const float* __restrict__ Whz, const float* __restrict__ bz,
    const float* __restrict__ Wxr, const float* __restrict__ Whr, const float* __restrict__ br,
    const float* __restrict__ WxH, const float* __restrict__ WrH, const float* __restrict__ bH,
    const float* __restrict__ Why, const float* __restrict__ by,
    float* __restrict__ out, int out_size)
{
    __shared__ __align__(16) float sw[6][HD][8];  // 0 Wxz | 1 Whz | 2 Wxr | 3 Whr | 4 WxH | 5 WrH
    __shared__ __align__(16) float sb[24];
    const int tid = threadIdx.x;
    const int layer = blockIdx.x / CS;
    const int c = blockIdx.x % CS;

    if (layer == 0) {
        for (int i = tid; i < HD * HD; i += blockDim.x) {
            ((float*)sw[0])[i] = Whz0[i];   // slot 0 = Whz0
            ((float*)sw[1])[i] = Whr0[i];   // slot 1 = Whr0
            ((float*)sw[2])[i] = WrH0[i];   // slot 2 = WrH0
        }
    } else {
        const int off = (layer - 1) * HD * HD;
        for (int i = tid; i < HD * HD; i += blockDim.x) {
            ((float*)sw[0])[i] = Wxz[off + i];
            ((float*)sw[1])[i] = Whz[off + i];
            ((float*)sw[2])[i] = Wxr[off + i];
            ((float*)sw[3])[i] = Whr[off + i];
            ((float*)sw[4])[i] = WxH[off + i];
            ((float*)sw[5])[i] = WrH[off + i];
        }
        if (tid < 8) {
            sb[tid]      = bz[(layer - 1) * 8 + tid];
            sb[8 + tid]  = br[(layer - 1) * 8 + tid];
            sb[16 + tid] = bH[(layer - 1) * 8 + tid];
        }
    }
    __syncthreads();

    const int pair = tid >> 1;
    const int hf = tid & 1;                  // owned cols: hf*4 .. hf*4+3
    const bool valid = (pair < BPC);
    const int b = c * BPC + (valid ? pair : BPC - 1);   // clamp; clamped lanes don't store
    const bool storer = valid && (hf == 0);

    float h[8];
    #pragma unroll
    for (int j = 0; j < 8; j++) h[j] = 0.f;

    unsigned int* pcnt = (layer < NL - 1) ? g_cnt + layer * NB + b : 0;
    float* outbase = (layer < NL - 1)
        ? g_hbuf + (((long long)layer * NS) * NB + b) * HD : 0;

    // own bias halves (layers > 0)
    u64 bz2[2], br2[2], bH2[2];
    if (layer > 0) {
        const u64* sb2 = (const u64*)sb;
        bz2[0] = sb2[hf * 2];     bz2[1] = sb2[hf * 2 + 1];
        br2[0] = sb2[4 + hf * 2]; br2[1] = sb2[4 + hf * 2 + 1];
        bH2[0] = sb2[8 + hf * 2]; bH2[1] = sb2[8 + hf * 2 + 1];
    }
    const int wo = hf * 4;   // own-column offset into weight rows

    if (layer == 0) {
        // -------- layer 0: prefetched xproj stream (own cols), no polling --------
        float4 vz, vr, vH;
        {
            const float* xp = g_xproj + (long long)b * 24;
            vz = __ldcg((const float4*)(xp + wo));
            vr = __ldcg((const float4*)(xp + 8 + wo));
            vH = __ldcg((const float4*)(xp + 16 + wo));
        }
        #pragma unroll 1
        for (int t = 0; t < NS; t++) {
            float4 nvz, nvr, nvH;
            if (t + 1 < NS) {
                const float* xp = g_xproj + ((long long)(t + 1) * NB + b) * 24;
                nvz = __ldcg((const float4*)(xp + wo));
                nvr = __ldcg((const float4*)(xp + 8 + wo));
                nvH = __ldcg((const float4*)(xp + 16 + wo));
            }
            u64 az[2], ar[2], aH[2];
            az[0] = pkab(vz.x, vz.y); az[1] = pkab(vz.z, vz.w);
            ar[0] = pkab(vr.x, vr.y); ar[1] = pkab(vr.z, vr.w);
            aH[0] = pkab(vH.x, vH.y); aH[1] = pkab(vH.z, vH.w);
            #pragma unroll
            for (int k = 0; k < 8; k++) {
                const u64 h2 = pk2(h[k]);
                fma4w(az, h2, sw[0][k] + wo);
                fma4w(ar, h2, sw[1][k] + wo);
            }
            float azf[4], arf[4], z[4], r[4];
            upk(az[0], azf[0], azf[1]); upk(az[1], azf[2], azf[3]);
            upk(ar[0], arf[0], arf[1]); upk(ar[1], arf[2], arf[3]);
            #pragma unroll
            for (int j = 0; j < 4; j++) { z[j] = sigm(azf[j]); r[j] = sigm(arf[j]); }
            // exchange r -> rh over all 8 rows
            float rf[8];
            #pragma unroll
            for (int j = 0; j < 4; j++) {
                const float ro = __shfl_xor_sync(0xffffffffu, r[j], 1);
                rf[wo + j] = r[j];
                rf[(4 - wo) + j] = ro;
            }
            #pragma unroll
            for (int k = 0; k < 8; k++) fma4w(aH, pk2(h[k] * rf[k]), sw[2][k] + wo);
            float aHf[4];
            upk(aH[0], aHf[0], aHf[1]); upk(aH[1], aHf[2], aHf[3]);
            float hn[4];
            #pragma unroll
            for (int j = 0; j < 4; j++) {
                const float Hc = tanh_hw(aHf[j]);
                hn[j] = fmaf(z[j], Hc - h[wo + j], h[wo + j]);
            }
            // exchange h halves -> full h
            #pragma unroll
            for (int j = 0; j < 4; j++) {
                const float ho = __shfl_xor_sync(0xffffffffu, hn[j], 1);
                h[wo + j] = hn[j];
                h[(4 - wo) + j] = ho;
            }
            if (storer) {
                float4* op = (float4*)(outbase + (long long)t * NB * HD);
                op[0] = make_float4(h[0], h[1], h[2], h[3]);
                op[1] = make_float4(h[4], h[5], h[6], h[7]);
                asm volatile("st.global.release.gpu.b32 [%0], %1;"
                             :: "l"(pcnt), "r"((unsigned int)(t + 1)) : "memory");
            }
            vz = nvz; vr = nvr; vH = nvH;
        }
    } else {
        // -------- layers 1..24: watermark consume + x/h split (own cols) --------
        const unsigned int* ccnt = g_cnt + (layer - 1) * NB + b;
        const float* inbase = g_hbuf + (((long long)(layer - 1) * NS) * NB + b) * HD;
        const bool producer = (layer < NL - 1);

        unsigned int avail = 0;
        auto wait_ge = [&](unsigned int want) {
            if (avail < want) {
                unsigned int vv;
                do {
                    asm volatile("ld.global.acquire.gpu.b32 %0, [%1];"
                                 : "=r"(vv) : "l"(ccnt) : "memory");
                } while (vv < want);
                avail = vv;
            }
        };

        // prologue: x(0) -> AX ; x(1) -> nx
        u64 AXz[2], AXr[2], AXH[2];
        float4 nxa, nxb;
        {
            wait_ge(1u);
            const float4* xi = (const float4*)inbase;
            float4 xa = __ldcg(xi), xb = __ldcg(xi + 1);
            const float xk[8] = {xa.x, xa.y, xa.z, xa.w, xb.x, xb.y, xb.z, xb.w};
            AXz[0] = bz2[0]; AXz[1] = bz2[1];
            AXr[0] = br2[0]; AXr[1] = br2[1];
            AXH[0] = bH2[0]; AXH[1] = bH2[1];
            #pragma unroll
            for (int k = 0; k < 8; k++) {
                const u64 x2 = pk2(xk[k]);
                fma4w(AXz, x2, sw[0][k] + wo);
                fma4w(AXr, x2, sw[2][k] + wo);
                fma4w(AXH, x2, sw[4][k] + wo);
            }
            wait_ge(2u);
            const float4* xi1 = (const float4*)(inbase + (long long)NB * HD);
            nxa = __ldcg(xi1); nxb = __ldcg(xi1 + 1);
        }

        #pragma unroll 1
        for (int t = 0; t < NS; t++) {
            // x-projections for step t+1 (independent of h)
            u64 NZ[2], NR[2], NH[2];
            if (t + 1 < NS) {
                const float xk[8] = {nxa.x, nxa.y, nxa.z, nxa.w, nxb.x, nxb.y, nxb.z, nxb.w};
                NZ[0] = bz2[0]; NZ[1] = bz2[1];
                NR[0] = br2[0]; NR[1] = br2[1];
                NH[0] = bH2[0]; NH[1] = bH2[1];
                #pragma unroll
                for (int k = 0; k < 8; k++) {
                    const u64 x2 = pk2(xk[k]);
                    fma4w(NZ, x2, sw[0][k] + wo);
                    fma4w(NR, x2, sw[2][k] + wo);
                    fma4w(NH, x2, sw[4][k] + wo);
                }
            }
            // watermark + prefetch x(t+2)
            float4 pxa, pxb;
            if (t + 2 < NS) {
                wait_ge((unsigned int)(t + 3));
                const float4* xi = (const float4*)(inbase + (long long)(t + 2) * NB * HD);
                pxa = __ldcg(xi); pxb = __ldcg(xi + 1);
            }
            // h-dependent part of step t
            u64 az[2], ar[2], aH[2];
            az[0] = AXz[0]; az[1] = AXz[1];
            ar[0] = AXr[0]; ar[1] = AXr[1];
            aH[0] = AXH[0]; aH[1] = AXH[1];
            #pragma unroll
            for (int k = 0; k < 8; k++) {
                const u64 h2 = pk2(h[k]);
                fma4w(az, h2, sw[1][k] + wo);
                fma4w(ar, h2, sw[3][k] + wo);
            }
            float azf[4], arf[4], z[4], r[4];
            upk(az[0], azf[0], azf[1]); upk(az[1], azf[2], azf[3]);
            upk(ar[0], arf[0], arf[1]); upk(ar[1], arf[2], arf[3]);
            #pragma unroll
            for (int j = 0; j < 4; j++) { z[j] = sigm(azf[j]); r[j] = sigm(arf[j]); }
            // exchange r -> full r vector
            float rf[8];
            #pragma unroll
            for (int j = 0; j < 4; j++) {
                const float ro = __shfl_xor_sync(0xffffffffu, r[j], 1);
                rf[wo + j] = r[j];
                rf[(4 - wo) + j] = ro;
            }
            #pragma unroll
            for (int k = 0; k < 8; k++) fma4w(aH, pk2(h[k] * rf[k]), sw[5][k] + wo);
            float aHf[4];
            upk(aH[0], aHf[0], aHf[1]); upk(aH[1], aHf[2], aHf[3]);
            float hn[4];
            #pragma unroll
            for (int j = 0; j < 4; j++) {
                const float Hc = tanh_hw(aHf[j]);
                hn[j] = fmaf(z[j], Hc - h[wo + j], h[wo + j]);
            }
            // exchange h halves -> full h
            #pragma unroll
            for (int j = 0; j < 4; j++) {
                const float ho = __shfl_xor_sync(0xffffffffu, hn[j], 1);
                h[wo + j] = hn[j];
                h[(4 - wo) + j] = ho;
            }
            if (producer && storer) {
                float4* op = (float4*)(outbase + (long long)t * NB * HD);
                op[0] = make_float4(h[0], h[1], h[2], h[3]);
                op[1] = make_float4(h[4], h[5], h[6], h[7]);
                asm volatile("st.global.release.gpu.b32 [%0], %1;"
                             :: "l"(pcnt), "r"((unsigned int)(t + 1)) : "memory");
            }
            // rotate pipeline state
            AXz[0] = NZ[0]; AXz[1] = NZ[1];
            AXr[0] = NR[0]; AXr[1] = NR[1];
            AXH[0] = NH[0]; AXH[1] = NH[1];
            nxa = pxa; nxb = pxb;
        }
    }

    if (storer) {
        if (out_size >= NB + NL * NB * HD) {
            float4* hp = (float4*)(out + NB + ((long long)layer * NB + b) * HD);
            hp[0] = make_float4(h[0], h[1], h[2], h[3]);
            hp[1] = make_float4(h[4], h[5], h[6], h[7]);
        }
        if (layer == NL - 1) {
            float acc = by[0];
            #pragma unroll
            for (int j = 0; j < 8; j++) acc = fmaf(h[j], Why[j], acc);
            out[b] = acc;
        }
    }
}

extern "C" void kernel_launch(void* const* d_in, const int* in_sizes, int n_in,
                              void* d_out, int out_size) {
    const int*   x    = (const int*)d_in[0];
    const float* emb  = (const float*)d_in[1];
    const float* Wxz0 = (const float*)d_in[2];
    const float* Whz0 = (const float*)d_in[3];
    const float* bz0  = (const float*)d_in[4];
    const float* Wxr0 = (const float*)d_in[5];
    const float* Whr0 = (const float*)d_in[6];
    const float* br0  = (const float*)d_in[7];
    const float* WxH0 = (const float*)d_in[8];
    const float* WrH0 = (const float*)d_in[9];
    const float* bH0  = (const float*)d_in[10];
    const float* Wxz  = (const float*)d_in[11];
    const float* Whz  = (const float*)d_in[12];
    const float* bz   = (const float*)d_in[13];
    const float* Wxr  = (const float*)d_in[14];
    const float* Whr  = (const float*)d_in[15];
    const float* br   = (const float*)d_in[16];
    const float* WxH  = (const float*)d_in[17];
    const float* WrH  = (const float*)d_in[18];
    const float* bH   = (const float*)d_in[19];
    const float* Why  = (const float*)d_in[20];
    const float* by   = (const float*)d_in[21];
    float* out = (float*)d_out;

    precompute_xproj<<<(NB * NS + 255) / 256, 256>>>(x, emb, Wxz0, bz0, Wxr0, br0, WxH0, bH0);
    gru_pipeline<<<NL * CS, TPB>>>(Whz0, Whr0, WrH0,
                                   Wxz, Whz, bz, Wxr, Whr, br, WxH, WrH, bH,
                                   Why, by, out, out_size);
}

// round 13
// speedup vs baseline: 1.3281x; 1.3281x over previous
#include <cuda_runtime.h>

#define NL 25
#define ED 64
#define HD 8
#define NB 1000
#define NS 512
#define CS 5          // CTAs (batch slices) per layer
#define BPC 200       // batch pairs per CTA
#define TPB 416       // 13 full warps; 400 active threads (200 pairs)

typedef unsigned long long u64;

// Scratch (static __device__ arrays; allocation-free per harness rules)
__device__ float g_xproj[NS * NB * 24];                    // layer-0 x-projections (+bias)
__device__ float g_hbuf[(NL - 1) * NS * NB * HD];          // inter-layer h buffers
__device__ unsigned int g_cnt[(NL - 1) * NB];              // per-(layer,b) progress counters

// ---------- f32x2 packed-FMA helpers ----------
__device__ __forceinline__ u64 pk2(float v) {
    u64 d; asm("mov.b64 %0,{%1,%1};" : "=l"(d) : "f"(v)); return d;
}
__device__ __forceinline__ u64 pkab(float a, float b) {
    u64 d; asm("mov.b64 %0,{%1,%2};" : "=l"(d) : "f"(a), "f"(b)); return d;
}
__device__ __forceinline__ void upk(u64 v, float& a, float& b) {
    asm("mov.b64 {%0,%1},%2;" : "=f"(a), "=f"(b) : "l"(v));
}
__device__ __forceinline__ u64 f2fma(u64 a, u64 b, u64 c) {
    u64 d; asm("fma.rn.f32x2 %0,%1,%2,%3;" : "=l"(d) : "l"(a), "l"(b), "l"(c)); return d;
}
__device__ __forceinline__ u64 f2add(u64 a, u64 b) {
    u64 d; asm("add.rn.f32x2 %0,%1,%2;" : "=l"(d) : "l"(a), "l"(b)); return d;
}
// acc[0..1] (4 floats) += s2 * w[0..3] at given float pointer (1x LDS.128)
__device__ __forceinline__ void fma4w(u64* acc, u64 s2, const float* w4) {
    ulonglong2 w = *(const ulonglong2*)(w4);
    acc[0] = f2fma(s2, w.x, acc[0]); acc[1] = f2fma(s2, w.y, acc[1]);
}
// full-row version (precompute kernel)
__device__ __forceinline__ void fma8w(u64* acc, u64 s2, const float* wrow) {
    ulonglong2 w01 = *(const ulonglong2*)(wrow);
    ulonglong2 w23 = *(const ulonglong2*)(wrow + 4);
    acc[0] = f2fma(s2, w01.x, acc[0]); acc[1] = f2fma(s2, w01.y, acc[1]);
    acc[2] = f2fma(s2, w23.x, acc[2]); acc[3] = f2fma(s2, w23.y, acc[3]);
}

// ---------- MUFU.TANH activations ----------
__device__ __forceinline__ float tanh_hw(float x) {
    float t; asm("tanh.approx.f32 %0,%1;" : "=f"(t) : "f"(x)); return t;
}
__device__ __forceinline__ float sigm(float x) {
    return fmaf(0.5f, tanh_hw(0.5f * x), 0.5f);
}

// ---------- precompute: layer-0 x-projections + counter clear ----------
__global__ void __launch_bounds__(256) precompute_xproj(
    const int* __restrict__ x, const float* __restrict__ emb,
    const float* __restrict__ Wxz0, const float* __restrict__ bz0,
    const float* __restrict__ Wxr0, const float* __restrict__ br0,
    const float* __restrict__ WxH0, const float* __restrict__ bH0)
{
    __shared__ __align__(16) float sw[3][ED][8];
    __shared__ __align__(16) float sb[24];
    const int tid = threadIdx.x;
    for (int i = tid; i < ED * HD; i += blockDim.x) {
        ((float*)sw[0])[i] = Wxz0[i];
        ((float*)sw[1])[i] = Wxr0[i];
        ((float*)sw[2])[i] = WxH0[i];
    }
    if (tid < 8) { sb[tid] = bz0[tid]; sb[8 + tid] = br0[tid]; sb[16 + tid] = bH0[tid]; }
    __syncthreads();

    const int gid = blockIdx.x * blockDim.x + tid;   // NB*NS = 512000 threads

    // clear counters: (NL-1)*NB = 24000 u32 = 6000 uint4
    if (gid < (NL - 1) * NB / 4) {
        ((uint4*)g_cnt)[gid] = make_uint4(0u, 0u, 0u, 0u);
    }

    if (gid >= NB * NS) return;
    const int b = gid / NS, t = gid % NS;
    const int idx = x[gid];
    const float4* e4 = (const float4*)(emb + (long long)idx * ED);

    const u64* sb2 = (const u64*)sb;
    u64 acc[12];
    #pragma unroll
    for (int j = 0; j < 12; j++) acc[j] = sb2[j];

    #pragma unroll
    for (int k4 = 0; k4 < ED / 4; k4++) {
        float4 ev = e4[k4];
        float es[4] = {ev.x, ev.y, ev.z, ev.w};
        #pragma unroll
        for (int q = 0; q < 4; q++) {
            const int k = k4 * 4 + q;
            const u64 s2 = pk2(es[q]);
            fma8w(acc,     s2, sw[0][k]);
            fma8w(acc + 4, s2, sw[1][k]);
            fma8w(acc + 8, s2, sw[2][k]);
        }
    }
    float o[24];
    #pragma unroll
    for (int j = 0; j < 12; j++) upk(acc[j], o[2 * j], o[2 * j + 1]);
    float4* o4 = (float4*)(g_xproj + ((long long)t * NB + b) * 24);
    #pragma unroll
    for (int j = 0; j < 6; j++)
        o4[j] = make_float4(o[4 * j], o[4 * j + 1], o[4 * j + 2], o[4 * j + 3]);
}

// ---------- persistent layer-pipelined GRU, k-aligned 2-thread split ----------
// Thread pair (b, hf): hf owns h/cols hf*4..hf*4+3 (k-half == col-half).
// h-part: each thread computes its k-half partial for all 8 cols into static
// (own, other) register pairs; one shfl_xor+add per gate combines. No r or h
// exchange on the recurrence chain.
__global__ void __launch_bounds__(TPB, 1) gru_pipeline(
    const float* __restrict__ Whz0, const float* __restrict__ Whr0, const float* __restrict__ WrH0,
    const float* __restrict__ Wxz, const float* __restrict__ Whz, const float* __restrict__ bz,
    const float* __restrict__ Wxr, const float* __restrict__ Whr, const float* __restrict__ br,
    const float* __restrict__ WxH, const float* __restrict__ WrH, const float* __restrict__ bH,
    const float* __restrict__ Why, const float* __restrict__ by,
    float* __restrict__ out, int out_size)
{
    __shared__ __align__(16) float sw[6][HD][8];  // 0 Wxz | 1 Whz | 2 Wxr | 3 Whr | 4 WxH | 5 WrH
    __shared__ __align__(16) float sb[24];
    const int tid = threadIdx.x;
    const int layer = blockIdx.x / CS;
    const int c = blockIdx.x % CS;

    if (layer == 0) {
        for (int i = tid; i < HD * HD; i += blockDim.x) {
            ((float*)sw[1])[i] = Whz0[i];   // slot 1 = Whz0 (match generic slots)
            ((float*)sw[3])[i] = Whr0[i];   // slot 3 = Whr0
            ((float*)sw[5])[i] = WrH0[i];   // slot 5 = WrH0
        }
    } else {
        const int off = (layer - 1) * HD * HD;
        for (int i = tid; i < HD * HD; i += blockDim.x) {
            ((float*)sw[0])[i] = Wxz[off + i];
            ((float*)sw[1])[i] = Whz[off + i];
            ((float*)sw[2])[i] = Wxr[off + i];
            ((float*)sw[3])[i] = Whr[off + i];
            ((float*)sw[4])[i] = WxH[off + i];
            ((float*)sw[5])[i] = WrH[off + i];
        }
        if (tid < 8) {
            sb[tid]      = bz[(layer - 1) * 8 + tid];
            sb[8 + tid]  = br[(layer - 1) * 8 + tid];
            sb[16 + tid] = bH[(layer - 1) * 8 + tid];
        }
    }
    __syncthreads();

    const int pair = tid >> 1;
    const int hf = tid & 1;
    const int wo = hf * 4;                   // own-column (and own-k) offset
    const int wq = 4 - wo;                   // partner-column offset
    const bool valid = (pair < BPC);
    const int b = c * BPC + (valid ? pair : BPC - 1);   // clamp; clamped lanes don't store
    const bool storer = valid && (hf == 0);

    // uniform weight-row base pointers (own/other col halves), k indexed by row*8
    const float* WXZ = (const float*)sw[0] + wo;   // x rows: full k, own cols
    const float* WXR = (const float*)sw[2] + wo;
    const float* WXH_ = (const float*)sw[4] + wo;
    const float* HZo = (const float*)sw[1] + wo * 8 + wo;   // h rows: own k...
    const float* HZq = (const float*)sw[1] + wo * 8 + wq;
    const float* HRo = (const float*)sw[3] + wo * 8 + wo;
    const float* HRq = (const float*)sw[3] + wo * 8 + wq;
    const float* RHo = (const float*)sw[5] + wo * 8 + wo;
    const float* RHq = (const float*)sw[5] + wo * 8 + wq;

    float h[4];   // own h (cols == k-half wo..wo+3)
    #pragma unroll
    for (int j = 0; j < 4; j++) h[j] = 0.f;

    unsigned int* pcnt = (layer < NL - 1) ? g_cnt + layer * NB + b : 0;
    float* outp = (layer < NL - 1)
        ? g_hbuf + (((long long)layer * NS) * NB + b) * HD : 0;

    // own bias halves (layers > 0)
    u64 bz2[2], br2[2], bH2[2];
    if (layer > 0) {
        const u64* sb2 = (const u64*)sb;
        bz2[0] = sb2[hf * 2];     bz2[1] = sb2[hf * 2 + 1];
        br2[0] = sb2[4 + hf * 2]; br2[1] = sb2[4 + hf * 2 + 1];
        bH2[0] = sb2[8 + hf * 2]; bH2[1] = sb2[8 + hf * 2 + 1];
    }

    if (layer == 0) {
        // -------- layer 0: precomputed x-projections (own cols), no polling --------
        const float* xp = g_xproj + (long long)b * 24;
        float4 vz = __ldcg((const float4*)(xp + wo));
        float4 vr = __ldcg((const float4*)(xp + 8 + wo));
        float4 vH = __ldcg((const float4*)(xp + 16 + wo));
        xp += NB * 24;

        #pragma unroll 1
        for (int t = 0; t < NS; t++) {
            float4 nvz, nvr, nvH;
            if (t + 1 < NS) {
                nvz = __ldcg((const float4*)(xp + wo));
                nvr = __ldcg((const float4*)(xp + 8 + wo));
                nvH = __ldcg((const float4*)(xp + 16 + wo));
                xp += NB * 24;
            }
            // h-part: own-k partials for all 8 cols (static own/oth split)
            u64 azo[2], azq[2], aro[2], arq[2];
            azo[0] = pkab(vz.x, vz.y); azo[1] = pkab(vz.z, vz.w);
            azq[0] = 0; azq[1] = 0;
            aro[0] = pkab(vr.x, vr.y); aro[1] = pkab(vr.z, vr.w);
            arq[0] = 0; arq[1] = 0;
            #pragma unroll
            for (int k = 0; k < 4; k++) {
                const u64 h2 = pk2(h[k]);
                fma4w(azo, h2, HZo + k * 8);
                fma4w(azq, h2, HZq + k * 8);
                fma4w(aro, h2, HRo + k * 8);
                fma4w(arq, h2, HRq + k * 8);
            }
            u64 az0 = f2add(azo[0], __shfl_xor_sync(0xffffffffu, azq[0], 1));
            u64 az1 = f2add(azo[1], __shfl_xor_sync(0xffffffffu, azq[1], 1));
            u64 ar0 = f2add(aro[0], __shfl_xor_sync(0xffffffffu, arq[0], 1));
            u64 ar1 = f2add(aro[1], __shfl_xor_sync(0xffffffffu, arq[1], 1));
            float azf[4], arf[4], z[4], r[4];
            upk(az0, azf[0], azf[1]); upk(az1, azf[2], azf[3]);
            upk(ar0, arf[0], arf[1]); upk(ar1, arf[2], arf[3]);
            #pragma unroll
            for (int j = 0; j < 4; j++) { z[j] = sigm(azf[j]); r[j] = sigm(arf[j]); }
            // aH: own (h*r) over own k
            u64 aHo[2], aHq[2];
            aHo[0] = pkab(vH.x, vH.y); aHo[1] = pkab(vH.z, vH.w);
            aHq[0] = 0; aHq[1] = 0;
            #pragma unroll
            for (int k = 0; k < 4; k++) {
                const u64 rh2 = pk2(h[k] * r[k]);
                fma4w(aHo, rh2, RHo + k * 8);
                fma4w(aHq, rh2, RHq + k * 8);
            }
            u64 aH0 = f2add(aHo[0], __shfl_xor_sync(0xffffffffu, aHq[0], 1));
            u64 aH1 = f2add(aHo[1], __shfl_xor_sync(0xffffffffu, aHq[1], 1));
            float aHf[4];
            upk(aH0, aHf[0], aHf[1]); upk(aH1, aHf[2], aHf[3]);
            #pragma unroll
            for (int j = 0; j < 4; j++) {
                const float Hc = tanh_hw(aHf[j]);
                h[j] = fmaf(z[j], Hc - h[j], h[j]);
            }
            // off-chain h exchange for the 32B store
            {
                u64 h01 = pkab(h[0], h[1]), h23 = pkab(h[2], h[3]);
                u64 p01 = __shfl_xor_sync(0xffffffffu, h01, 1);
                u64 p23 = __shfl_xor_sync(0xffffffffu, h23, 1);
                if (storer) {
                    float a0, a1, a2, a3, b0v, b1v, b2v, b3v;
                    upk(h01, a0, a1); upk(h23, a2, a3);
                    upk(p01, b0v, b1v); upk(p23, b2v, b3v);
                    ((float4*)outp)[0] = make_float4(a0, a1, a2, a3);
                    ((float4*)outp)[1] = make_float4(b0v, b1v, b2v, b3v);
                    asm volatile("st.global.release.gpu.b32 [%0], %1;"
                                 :: "l"(pcnt), "r"((unsigned int)(t + 1)) : "memory");
                }
                outp += NB * HD;
            }
            vz = nvz; vr = nvr; vH = nvH;
        }
    } else {
        // -------- layers 1..24: watermark consume, x/h split, k-split h-part ------
        const unsigned int* ccnt = g_cnt + (layer - 1) * NB + b;
        const float* inp = g_hbuf + (((long long)(layer - 1) * NS) * NB + b) * HD;
        const bool producer = (layer < NL - 1);

        unsigned int avail = 0;
        auto wait_ge = [&](unsigned int want) {
            if (avail < want) {
                unsigned int vv;
                do {
                    asm volatile("ld.global.acquire.gpu.b32 %0, [%1];"
                                 : "=r"(vv) : "l"(ccnt) : "memory");
                } while (vv < want);
                avail = vv;
            }
        };

        // x-projection of x(t) for own cols, full k
        u64 XZ[2], XR[2], XH[2];
        float4 nxa, nxb;   // x(t+1)
        {
            wait_ge(1u);
            float4 xa = __ldcg((const float4*)inp);
            float4 xb = __ldcg((const float4*)inp + 1);
            inp += NB * HD;
            const float xk[8] = {xa.x, xa.y, xa.z, xa.w, xb.x, xb.y, xb.z, xb.w};
            XZ[0] = bz2[0]; XZ[1] = bz2[1];
            XR[0] = br2[0]; XR[1] = br2[1];
            XH[0] = bH2[0]; XH[1] = bH2[1];
            #pragma unroll
            for (int k = 0; k < 8; k++) {
                const u64 x2 = pk2(xk[k]);
                fma4w(XZ, x2, WXZ + k * 8);
                fma4w(XR, x2, WXR + k * 8);
                fma4w(XH, x2, WXH_ + k * 8);
            }
            wait_ge(2u);
            nxa = __ldcg((const float4*)inp);
            nxb = __ldcg((const float4*)inp + 1);
            inp += NB * HD;
        }

        #pragma unroll 1
        for (int t = 0; t < NS; t++) {
            // x-projections for t+1
            u64 NZ[2], NR[2], NH[2];
            if (t + 1 < NS) {
                const float xk[8] = {nxa.x, nxa.y, nxa.z, nxa.w, nxb.x, nxb.y, nxb.z, nxb.w};
                NZ[0] = bz2[0]; NZ[1] = bz2[1];
                NR[0] = br2[0]; NR[1] = br2[1];
                NH[0] = bH2[0]; NH[1] = bH2[1];
                #pragma unroll
                for (int k = 0; k < 8; k++) {
                    const u64 x2 = pk2(xk[k]);
                    fma4w(NZ, x2, WXZ + k * 8);
                    fma4w(NR, x2, WXR + k * 8);
                    fma4w(NH, x2, WXH_ + k * 8);
                }
            }
            // watermark + prefetch x(t+2)
            float4 pxa, pxb;
            if (t + 2 < NS) {
                wait_ge((unsigned int)(t + 3));
                pxa = __ldcg((const float4*)inp);
                pxb = __ldcg((const float4*)inp + 1);
                inp += NB * HD;
            }
            // h-part: own-k partials for all 8 cols
            u64 azo[2], azq[2], aro[2], arq[2];
            azo[0] = XZ[0]; azo[1] = XZ[1]; azq[0] = 0; azq[1] = 0;
            aro[0] = XR[0]; aro[1] = XR[1]; arq[0] = 0; arq[1] = 0;
            #pragma unroll
            for (int k = 0; k < 4; k++) {
                const u64 h2 = pk2(h[k]);
                fma4w(azo, h2, HZo + k * 8);
                fma4w(azq, h2, HZq + k * 8);
                fma4w(aro, h2, HRo + k * 8);
                fma4w(arq, h2, HRq + k * 8);
            }
            u64 az0 = f2add(azo[0], __shfl_xor_sync(0xffffffffu, azq[0], 1));
            u64 az1 = f2add(azo[1], __shfl_xor_sync(0xffffffffu, azq[1], 1));
            u64 ar0 = f2add(aro[0], __shfl_xor_sync(0xffffffffu, arq[0], 1));
            u64 ar1 = f2add(aro[1], __shfl_xor_sync(0xffffffffu, arq[1], 1));
            float azf[4], arf[4], z[4], r[4];
            upk(az0, azf[0], azf[1]); upk(az1, azf[2], azf[3]);
            upk(ar0, arf[0], arf[1]); upk(ar1, arf[2], arf[3]);
            #pragma unroll
            for (int j = 0; j < 4; j++) { z[j] = sigm(azf[j]); r[j] = sigm(arf[j]); }
            u64 aHo[2], aHq[2];
            aHo[0] = XH[0]; aHo[1] = XH[1]; aHq[0] = 0; aHq[1] = 0;
            #pragma unroll
            for (int k = 0; k < 4; k++) {
                const u64 rh2 = pk2(h[k] * r[k]);
                fma4w(aHo, rh2, RHo + k * 8);
                fma4w(aHq, rh2, RHq + k * 8);
            }
            u64 aH0 = f2add(aHo[0], __shfl_xor_sync(0xffffffffu, aHq[0], 1));
            u64 aH1 = f2add(aHo[1], __shfl_xor_sync(0xffffffffu, aHq[1], 1));
            float aHf[4];
            upk(aH0, aHf[0], aHf[1]); upk(aH1, aHf[2], aHf[3]);
            #pragma unroll
            for (int j = 0; j < 4; j++) {
                const float Hc = tanh_hw(aHf[j]);
                h[j] = fmaf(z[j], Hc - h[j], h[j]);
            }
            if (producer) {
                u64 h01 = pkab(h[0], h[1]), h23 = pkab(h[2], h[3]);
                u64 p01 = __shfl_xor_sync(0xffffffffu, h01, 1);
                u64 p23 = __shfl_xor_sync(0xffffffffu, h23, 1);
                if (storer) {
                    float a0, a1, a2, a3, b0v, b1v, b2v, b3v;
                    upk(h01, a0, a1); upk(h23, a2, a3);
                    upk(p01, b0v, b1v); upk(p23, b2v, b3v);
                    ((float4*)outp)[0] = make_float4(a0, a1, a2, a3);
                    ((float4*)outp)[1] = make_float4(b0v, b1v, b2v, b3v);
                    asm volatile("st.global.release.gpu.b32 [%0], %1;"
                                 :: "l"(pcnt), "r"((unsigned int)(t + 1)) : "memory");
                }
                outp += NB * HD;
            }
            XZ[0] = NZ[0]; XZ[1] = NZ[1];
            XR[0] = NR[0]; XR[1] = NR[1];
            XH[0] = NH[0]; XH[1] = NH[1];
            nxa = pxa; nxb = pxb;
        }
    }

    // final full-h assembly (off-loop) and outputs
    {
        u64 h01 = pkab(h[0], h[1]), h23 = pkab(h[2], h[3]);
        u64 p01 = __shfl_xor_sync(0xffffffffu, h01, 1);
        u64 p23 = __shfl_xor_sync(0xffffffffu, h23, 1);
        if (storer) {
            float a0, a1, a2, a3, b0v, b1v, b2v, b3v;
            upk(h01, a0, a1); upk(h23, a2, a3);
            upk(p01, b0v, b1v); upk(p23, b2v, b3v);
            if (out_size >= NB + NL * NB * HD) {
                float4* hp = (float4*)(out + NB + ((long long)layer * NB + b) * HD);
                hp[0] = make_float4(a0, a1, a2, a3);
                hp[1] = make_float4(b0v, b1v, b2v, b3v);
            }
            if (layer == NL - 1) {
                float acc = by[0];
                acc = fmaf(a0, Why[0], acc); acc = fmaf(a1, Why[1], acc);
                acc = fmaf(a2, Why[2], acc); acc = fmaf(a3, Why[3], acc);
                acc = fmaf(b0v, Why[4], acc); acc = fmaf(b1v, Why[5], acc);
                acc = fmaf(b2v, Why[6], acc); acc = fmaf(b3v, Why[7], acc);
                out[b] = acc;
            }
        }
    }
}

extern "C" void kernel_launch(void* const* d_in, const int* in_sizes, int n_in,
                              void* d_out, int out_size) {
    const int*   x    = (const int*)d_in[0];
    const float* emb  = (const float*)d_in[1];
    const float* Wxz0 = (const float*)d_in[2];
    const float* Whz0 = (const float*)d_in[3];
    const float* bz0  = (const float*)d_in[4];
    const float* Wxr0 = (const float*)d_in[5];
    const float* Whr0 = (const float*)d_in[6];
    const float* br0  = (const float*)d_in[7];
    const float* WxH0 = (const float*)d_in[8];
    const float* WrH0 = (const float*)d_in[9];
    const float* bH0  = (const float*)d_in[10];
    const float* Wxz  = (const float*)d_in[11];
    const float* Whz  = (const float*)d_in[12];
    const float* bz   = (const float*)d_in[13];
    const float* Wxr  = (const float*)d_in[14];
    const float* Whr  = (const float*)d_in[15];
    const float* br   = (const float*)d_in[16];
    const float* WxH  = (const float*)d_in[17];
    const float* WrH  = (const float*)d_in[18];
    const float* bH   = (const float*)d_in[19];
    const float* Why  = (const float*)d_in[20];
    const float* by   = (const float*)d_in[21];
    float* out = (float*)d_out;

    precompute_xproj<<<(NB * NS + 255) / 256, 256>>>(x, emb, Wxz0, bz0, Wxr0, br0, WxH0, bH0);
    gru_pipeline<<<NL * CS, TPB>>>(Whz0, Whr0, WrH0,
                                   Wxz, Whz, bz, Wxr, Whr, br, WxH, WrH, bH,
                                   Why, by, out, out_size);
}

// round 14
// speedup vs baseline: 1.3294x; 1.0010x over previous
#include <cuda_runtime.h>

#define NL 25
#define ED 64
#define HD 8
#define NB 1000
#define NS 512
#define CS 5          // CTAs (batch slices) per layer
#define BPC 200       // batch pairs per CTA
#define TPB 416       // 13 full warps; 400 active threads (200 pairs)

typedef unsigned long long u64;

// Scratch (static __device__ arrays; allocation-free per harness rules)
__device__ float g_xproj[NS * NB * 24];                    // layer-0 x-projections (+bias)
__device__ float g_hbuf[(NL - 1) * NS * NB * HD];          // inter-layer h buffers
__device__ unsigned int g_cnt[(NL - 1) * NB];              // per-(layer,b) progress counters

// ---------- f32x2 packed-FMA helpers ----------
__device__ __forceinline__ u64 pk2(float v) {
    u64 d; asm("mov.b64 %0,{%1,%1};" : "=l"(d) : "f"(v)); return d;
}
__device__ __forceinline__ u64 pkab(float a, float b) {
    u64 d; asm("mov.b64 %0,{%1,%2};" : "=l"(d) : "f"(a), "f"(b)); return d;
}
__device__ __forceinline__ void upk(u64 v, float& a, float& b) {
    asm("mov.b64 {%0,%1},%2;" : "=f"(a), "=f"(b) : "l"(v));
}
__device__ __forceinline__ u64 f2fma(u64 a, u64 b, u64 c) {
    u64 d; asm("fma.rn.f32x2 %0,%1,%2,%3;" : "=l"(d) : "l"(a), "l"(b), "l"(c)); return d;
}
__device__ __forceinline__ u64 f2add(u64 a, u64 b) {
    u64 d; asm("add.rn.f32x2 %0,%1,%2;" : "=l"(d) : "l"(a), "l"(b)); return d;
}
// acc[0..1] (4 floats) += s2 * w[0..3] at given float pointer (1x LDS.128)
__device__ __forceinline__ void fma4w(u64* acc, u64 s2, const float* w4) {
    ulonglong2 w = *(const ulonglong2*)(w4);
    acc[0] = f2fma(s2, w.x, acc[0]); acc[1] = f2fma(s2, w.y, acc[1]);
}
// register-resident weight variant
__device__ __forceinline__ void fma4r(u64* acc, u64 s2, u64 w0, u64 w1) {
    acc[0] = f2fma(s2, w0, acc[0]); acc[1] = f2fma(s2, w1, acc[1]);
}
// full-row version (precompute kernel)
__device__ __forceinline__ void fma8w(u64* acc, u64 s2, const float* wrow) {
    ulonglong2 w01 = *(const ulonglong2*)(wrow);
    ulonglong2 w23 = *(const ulonglong2*)(wrow + 4);
    acc[0] = f2fma(s2, w01.x, acc[0]); acc[1] = f2fma(s2, w01.y, acc[1]);
    acc[2] = f2fma(s2, w23.x, acc[2]); acc[3] = f2fma(s2, w23.y, acc[3]);
}

// ---------- MUFU.TANH activations ----------
__device__ __forceinline__ float tanh_hw(float x) {
    float t; asm("tanh.approx.f32 %0,%1;" : "=f"(t) : "f"(x)); return t;
}
__device__ __forceinline__ float sigm(float x) {
    return fmaf(0.5f, tanh_hw(0.5f * x), 0.5f);
}

__device__ __forceinline__ unsigned int acq_ld(const unsigned int* p) {
    unsigned int v;
    asm volatile("ld.global.acquire.gpu.b32 %0, [%1];" : "=r"(v) : "l"(p) : "memory");
    return v;
}

// ---------- precompute: layer-0 x-projections + counter clear ----------
__global__ void __launch_bounds__(256) precompute_xproj(
    const int* __restrict__ x, const float* __restrict__ emb,
    const float* __restrict__ Wxz0, const float* __restrict__ bz0,
    const float* __restrict__ Wxr0, const float* __restrict__ br0,
    const float* __restrict__ WxH0, const float* __restrict__ bH0)
{
    __shared__ __align__(16) float sw[3][ED][8];
    __shared__ __align__(16) float sb[24];
    const int tid = threadIdx.x;
    for (int i = tid; i < ED * HD; i += blockDim.x) {
        ((float*)sw[0])[i] = Wxz0[i];
        ((float*)sw[1])[i] = Wxr0[i];
        ((float*)sw[2])[i] = WxH0[i];
    }
    if (tid < 8) { sb[tid] = bz0[tid]; sb[8 + tid] = br0[tid]; sb[16 + tid] = bH0[tid]; }
    __syncthreads();

    const int gid = blockIdx.x * blockDim.x + tid;   // NB*NS = 512000 threads

    if (gid < (NL - 1) * NB / 4) {
        ((uint4*)g_cnt)[gid] = make_uint4(0u, 0u, 0u, 0u);
    }

    if (gid >= NB * NS) return;
    const int b = gid / NS, t = gid % NS;
    const int idx = x[gid];
    const float4* e4 = (const float4*)(emb + (long long)idx * ED);

    const u64* sb2 = (const u64*)sb;
    u64 acc[12];
    #pragma unroll
    for (int j = 0; j < 12; j++) acc[j] = sb2[j];

    #pragma unroll
    for (int k4 = 0; k4 < ED / 4; k4++) {
        float4 ev = e4[k4];
        float es[4] = {ev.x, ev.y, ev.z, ev.w};
        #pragma unroll
        for (int q = 0; q < 4; q++) {
            const int k = k4 * 4 + q;
            const u64 s2 = pk2(es[q]);
            fma8w(acc,     s2, sw[0][k]);
            fma8w(acc + 4, s2, sw[1][k]);
            fma8w(acc + 8, s2, sw[2][k]);
        }
    }
    float o[24];
    #pragma unroll
    for (int j = 0; j < 12; j++) upk(acc[j], o[2 * j], o[2 * j + 1]);
    float4* o4 = (float4*)(g_xproj + ((long long)t * NB + b) * 24);
    #pragma unroll
    for (int j = 0; j < 6; j++)
        o4[j] = make_float4(o[4 * j], o[4 * j + 1], o[4 * j + 2], o[4 * j + 3]);
}

// ---------- persistent layer-pipelined GRU, k-aligned 2-thread split ----------
// Early-issue/late-check counter poll; WrH register-resident.
__global__ void __launch_bounds__(TPB, 1) gru_pipeline(
    const float* __restrict__ Whz0, const float* __restrict__ Whr0, const float* __restrict__ WrH0,
    const float* __restrict__ Wxz, const float* __restrict__ Whz, const float* __restrict__ bz,
    const float* __restrict__ Wxr, const float* __restrict__ Whr, const float* __restrict__ br,
    const float* __restrict__ WxH, const float* __restrict__ WrH, const float* __restrict__ bH,
    const float* __restrict__ Why, const float* __restrict__ by,
    float* __restrict__ out, int out_size)
{
    __shared__ __align__(16) float sw[6][HD][8];  // 0 Wxz | 1 Whz | 2 Wxr | 3 Whr | 4 WxH | 5 WrH
    __shared__ __align__(16) float sb[24];
    const int tid = threadIdx.x;
    const int layer = blockIdx.x / CS;
    const int c = blockIdx.x % CS;

    if (layer == 0) {
        for (int i = tid; i < HD * HD; i += blockDim.x) {
            ((float*)sw[1])[i] = Whz0[i];   // slot 1 = Whz0
            ((float*)sw[3])[i] = Whr0[i];   // slot 3 = Whr0
            ((float*)sw[5])[i] = WrH0[i];   // slot 5 = WrH0
        }
        if (tid < 24) sb[tid] = 0.f;
    } else {
        const int off = (layer - 1) * HD * HD;
        for (int i = tid; i < HD * HD; i += blockDim.x) {
            ((float*)sw[0])[i] = Wxz[off + i];
            ((float*)sw[1])[i] = Whz[off + i];
            ((float*)sw[2])[i] = Wxr[off + i];
            ((float*)sw[3])[i] = Whr[off + i];
            ((float*)sw[4])[i] = WxH[off + i];
            ((float*)sw[5])[i] = WrH[off + i];
        }
        if (tid < 8) {
            sb[tid]      = bz[(layer - 1) * 8 + tid];
            sb[8 + tid]  = br[(layer - 1) * 8 + tid];
            sb[16 + tid] = bH[(layer - 1) * 8 + tid];
        }
    }
    __syncthreads();

    const int pair = tid >> 1;
    const int hf = tid & 1;
    const int wo = hf * 4;                   // own-column (and own-k) offset
    const int wq = 4 - wo;                   // partner-column offset
    const bool valid = (pair < BPC);
    const int b = c * BPC + (valid ? pair : BPC - 1);   // clamp; clamped lanes don't store
    const bool storer = valid && (hf == 0);

    // uniform weight-row base pointers
    const float* WXZ = (const float*)sw[0] + wo;   // x rows: full k, own cols
    const float* WXR = (const float*)sw[2] + wo;
    const float* WXH_ = (const float*)sw[4] + wo;
    const float* HZo = (const float*)sw[1] + wo * 8 + wo;   // h rows: own k
    const float* HZq = (const float*)sw[1] + wo * 8 + wq;
    const float* HRo = (const float*)sw[3] + wo * 8 + wo;
    const float* HRq = (const float*)sw[3] + wo * 8 + wq;

    // WrH own-k rows -> registers (chain segment after r-sigmoid)
    u64 RHo_r[4][2], RHq_r[4][2];
    {
        const float* RHo = (const float*)sw[5] + wo * 8 + wo;
        const float* RHq = (const float*)sw[5] + wo * 8 + wq;
        #pragma unroll
        for (int k = 0; k < 4; k++) {
            ulonglong2 a = *(const ulonglong2*)(RHo + k * 8);
            ulonglong2 d = *(const ulonglong2*)(RHq + k * 8);
            RHo_r[k][0] = a.x; RHo_r[k][1] = a.y;
            RHq_r[k][0] = d.x; RHq_r[k][1] = d.y;
        }
    }
    const u64* sbz = (const u64*)sb + hf * 2;        // own bias halves (LDS each step)
    const u64* sbr = (const u64*)sb + 4 + hf * 2;
    const u64* sbH = (const u64*)sb + 8 + hf * 2;

    float h[4];   // own h (cols == k-half wo..wo+3)
    #pragma unroll
    for (int j = 0; j < 4; j++) h[j] = 0.f;

    unsigned int* pcnt = (layer < NL - 1) ? g_cnt + layer * NB + b : 0;
    float* outp = (layer < NL - 1)
        ? g_hbuf + (((long long)layer * NS) * NB + b) * HD : 0;

    if (layer == 0) {
        // -------- layer 0: precomputed x-projections (own cols), no polling --------
        const float* xp = g_xproj + (long long)b * 24;
        float4 vz = __ldcg((const float4*)(xp + wo));
        float4 vr = __ldcg((const float4*)(xp + 8 + wo));
        float4 vH = __ldcg((const float4*)(xp + 16 + wo));
        xp += NB * 24;

        #pragma unroll 1
        for (int t = 0; t < NS; t++) {
            float4 nvz, nvr, nvH;
            if (t + 1 < NS) {
                nvz = __ldcg((const float4*)(xp + wo));
                nvr = __ldcg((const float4*)(xp + 8 + wo));
                nvH = __ldcg((const float4*)(xp + 16 + wo));
                xp += NB * 24;
            }
            u64 azo[2], azq[2], aro[2], arq[2];
            azo[0] = pkab(vz.x, vz.y); azo[1] = pkab(vz.z, vz.w);
            azq[0] = 0; azq[1] = 0;
            aro[0] = pkab(vr.x, vr.y); aro[1] = pkab(vr.z, vr.w);
            arq[0] = 0; arq[1] = 0;
            #pragma unroll
            for (int k = 0; k < 4; k++) {
                const u64 h2 = pk2(h[k]);
                fma4w(azo, h2, HZo + k * 8);
                fma4w(azq, h2, HZq + k * 8);
                fma4w(aro, h2, HRo + k * 8);
                fma4w(arq, h2, HRq + k * 8);
            }
            u64 az0 = f2add(azo[0], __shfl_xor_sync(0xffffffffu, azq[0], 1));
            u64 az1 = f2add(azo[1], __shfl_xor_sync(0xffffffffu, azq[1], 1));
            u64 ar0 = f2add(aro[0], __shfl_xor_sync(0xffffffffu, arq[0], 1));
            u64 ar1 = f2add(aro[1], __shfl_xor_sync(0xffffffffu, arq[1], 1));
            float azf[4], arf[4], z[4], r[4];
            upk(az0, azf[0], azf[1]); upk(az1, azf[2], azf[3]);
            upk(ar0, arf[0], arf[1]); upk(ar1, arf[2], arf[3]);
            #pragma unroll
            for (int j = 0; j < 4; j++) { z[j] = sigm(azf[j]); r[j] = sigm(arf[j]); }
            u64 aHo[2], aHq[2];
            aHo[0] = pkab(vH.x, vH.y); aHo[1] = pkab(vH.z, vH.w);
            aHq[0] = 0; aHq[1] = 0;
            #pragma unroll
            for (int k = 0; k < 4; k++) {
                const u64 rh2 = pk2(h[k] * r[k]);
                fma4r(aHo, rh2, RHo_r[k][0], RHo_r[k][1]);
                fma4r(aHq, rh2, RHq_r[k][0], RHq_r[k][1]);
            }
            u64 aH0 = f2add(aHo[0], __shfl_xor_sync(0xffffffffu, aHq[0], 1));
            u64 aH1 = f2add(aHo[1], __shfl_xor_sync(0xffffffffu, aHq[1], 1));
            float aHf[4];
            upk(aH0, aHf[0], aHf[1]); upk(aH1, aHf[2], aHf[3]);
            #pragma unroll
            for (int j = 0; j < 4; j++) {
                const float Hc = tanh_hw(aHf[j]);
                h[j] = fmaf(z[j], Hc - h[j], h[j]);
            }
            {
                u64 h01 = pkab(h[0], h[1]), h23 = pkab(h[2], h[3]);
                u64 p01 = __shfl_xor_sync(0xffffffffu, h01, 1);
                u64 p23 = __shfl_xor_sync(0xffffffffu, h23, 1);
                if (storer) {
                    float a0, a1, a2, a3, b0v, b1v, b2v, b3v;
                    upk(h01, a0, a1); upk(h23, a2, a3);
                    upk(p01, b0v, b1v); upk(p23, b2v, b3v);
                    ((float4*)outp)[0] = make_float4(a0, a1, a2, a3);
                    ((float4*)outp)[1] = make_float4(b0v, b1v, b2v, b3v);
                    asm volatile("st.global.release.gpu.b32 [%0], %1;"
                                 :: "l"(pcnt), "r"((unsigned int)(t + 1)) : "memory");
                }
                outp += NB * HD;
            }
            vz = nvz; vr = nvr; vH = nvH;
        }
    } else {
        // -------- layers 1..24: early-poll watermark consume --------
        const unsigned int* ccnt = g_cnt + (layer - 1) * NB + b;
        const float* inp = g_hbuf + (((long long)(layer - 1) * NS) * NB + b) * HD;
        const bool producer = (layer < NL - 1);

        unsigned int avail = 0;

        // x-projection of x(t) for own cols, full k
        u64 XZ[2], XR[2], XH[2];
        float4 nxa, nxb;   // x(t+1)
        {
            while (avail < 1u) avail = acq_ld(ccnt);
            float4 xa = __ldcg((const float4*)inp);
            float4 xb = __ldcg((const float4*)inp + 1);
            inp += NB * HD;
            const float xk[8] = {xa.x, xa.y, xa.z, xa.w, xb.x, xb.y, xb.z, xb.w};
            XZ[0] = sbz[0]; XZ[1] = sbz[1];
            XR[0] = sbr[0]; XR[1] = sbr[1];
            XH[0] = sbH[0]; XH[1] = sbH[1];
            #pragma unroll
            for (int k = 0; k < 8; k++) {
                const u64 x2 = pk2(xk[k]);
                fma4w(XZ, x2, WXZ + k * 8);
                fma4w(XR, x2, WXR + k * 8);
                fma4w(XH, x2, WXH_ + k * 8);
            }
            while (avail < 2u) avail = acq_ld(ccnt);
            nxa = __ldcg((const float4*)inp);
            nxb = __ldcg((const float4*)inp + 1);
            inp += NB * HD;
        }

        #pragma unroll 1
        for (int t = 0; t < NS; t++) {
            // early-issue counter load (checked after x-proj compute)
            const unsigned int want = (unsigned int)(t + 3);
            const bool needp = (t + 2 < NS) && (avail < want);
            unsigned int cv = 0;
            if (needp) cv = acq_ld(ccnt);

            // x-projections for t+1 (independent of h and of the poll)
            u64 NZ[2], NR[2], NH[2];
            if (t + 1 < NS) {
                const float xk[8] = {nxa.x, nxa.y, nxa.z, nxa.w, nxb.x, nxb.y, nxb.z, nxb.w};
                NZ[0] = sbz[0]; NZ[1] = sbz[1];
                NR[0] = sbr[0]; NR[1] = sbr[1];
                NH[0] = sbH[0]; NH[1] = sbH[1];
                #pragma unroll
                for (int k = 0; k < 8; k++) {
                    const u64 x2 = pk2(xk[k]);
                    fma4w(NZ, x2, WXZ + k * 8);
                    fma4w(NR, x2, WXR + k * 8);
                    fma4w(NH, x2, WXH_ + k * 8);
                }
            }
            // late check + prefetch x(t+2)
            float4 pxa, pxb;
            if (t + 2 < NS) {
                if (needp) {
                    while (cv < want) cv = acq_ld(ccnt);
                    avail = cv;
                }
                pxa = __ldcg((const float4*)inp);
                pxb = __ldcg((const float4*)inp + 1);
                inp += NB * HD;
            }
            // h-dependent part of step t
            u64 azo[2], azq[2], aro[2], arq[2];
            azo[0] = XZ[0]; azo[1] = XZ[1]; azq[0] = 0; azq[1] = 0;
            aro[0] = XR[0]; aro[1] = XR[1]; arq[0] = 0; arq[1] = 0;
            #pragma unroll
            for (int k = 0; k < 4; k++) {
                const u64 h2 = pk2(h[k]);
                fma4w(azo, h2, HZo + k * 8);
                fma4w(azq, h2, HZq + k * 8);
                fma4w(aro, h2, HRo + k * 8);
                fma4w(arq, h2, HRq + k * 8);
            }
            u64 az0 = f2add(azo[0], __shfl_xor_sync(0xffffffffu, azq[0], 1));
            u64 az1 = f2add(azo[1], __shfl_xor_sync(0xffffffffu, azq[1], 1));
            u64 ar0 = f2add(aro[0], __shfl_xor_sync(0xffffffffu, arq[0], 1));
            u64 ar1 = f2add(aro[1], __shfl_xor_sync(0xffffffffu, arq[1], 1));
            float azf[4], arf[4], z[4], r[4];
            upk(az0, azf[0], azf[1]); upk(az1, azf[2], azf[3]);
            upk(ar0, arf[0], arf[1]); upk(ar1, arf[2], arf[3]);
            #pragma unroll
            for (int j = 0; j < 4; j++) { z[j] = sigm(azf[j]); r[j] = sigm(arf[j]); }
            u64 aHo[2], aHq[2];
            aHo[0] = XH[0]; aHo[1] = XH[1]; aHq[0] = 0; aHq[1] = 0;
            #pragma unroll
            for (int k = 0; k < 4; k++) {
                const u64 rh2 = pk2(h[k] * r[k]);
                fma4r(aHo, rh2, RHo_r[k][0], RHo_r[k][1]);
                fma4r(aHq, rh2, RHq_r[k][0], RHq_r[k][1]);
            }
            u64 aH0 = f2add(aHo[0], __shfl_xor_sync(0xffffffffu, aHq[0], 1));
            u64 aH1 = f2add(aHo[1], __shfl_xor_sync(0xffffffffu, aHq[1], 1));
            float aHf[4];
            upk(aH0, aHf[0], aHf[1]); upk(aH1, aHf[2], aHf[3]);
            #pragma unroll
            for (int j = 0; j < 4; j++) {
                const float Hc = tanh_hw(aHf[j]);
                h[j] = fmaf(z[j], Hc - h[j], h[j]);
            }
            if (producer) {
                u64 h01 = pkab(h[0], h[1]), h23 = pkab(h[2], h[3]);
                u64 p01 = __shfl_xor_sync(0xffffffffu, h01, 1);
                u64 p23 = __shfl_xor_sync(0xffffffffu, h23, 1);
                if (storer) {
                    float a0, a1, a2, a3, b0v, b1v, b2v, b3v;
                    upk(h01, a0, a1); upk(h23, a2, a3);
                    upk(p01, b0v, b1v); upk(p23, b2v, b3v);
                    ((float4*)outp)[0] = make_float4(a0, a1, a2, a3);
                    ((float4*)outp)[1] = make_float4(b0v, b1v, b2v, b3v);
                    asm volatile("st.global.release.gpu.b32 [%0], %1;"
                                 :: "l"(pcnt), "r"((unsigned int)(t + 1)) : "memory");
                }
                outp += NB * HD;
            }
            XZ[0] = NZ[0]; XZ[1] = NZ[1];
            XR[0] = NR[0]; XR[1] = NR[1];
            XH[0] = NH[0]; XH[1] = NH[1];
            nxa = pxa; nxb = pxb;
        }
    }

    // final full-h assembly (off-loop) and outputs
    {
        u64 h01 = pkab(h[0], h[1]), h23 = pkab(h[2], h[3]);
        u64 p01 = __shfl_xor_sync(0xffffffffu, h01, 1);
        u64 p23 = __shfl_xor_sync(0xffffffffu, h23, 1);
        if (storer) {
            float a0, a1, a2, a3, b0v, b1v, b2v, b3v;
            upk(h01, a0, a1); upk(h23, a2, a3);
            upk(p01, b0v, b1v); upk(p23, b2v, b3v);
            if (out_size >= NB + NL * NB * HD) {
                float4* hp = (float4*)(out + NB + ((long long)layer * NB + b) * HD);
                hp[0] = make_float4(a0, a1, a2, a3);
                hp[1] = make_float4(b0v, b1v, b2v, b3v);
            }
            if (layer == NL - 1) {
                float acc = by[0];
                acc = fmaf(a0, Why[0], acc); acc = fmaf(a1, Why[1], acc);
                acc = fmaf(a2, Why[2], acc); acc = fmaf(a3, Why[3], acc);
                acc = fmaf(b0v, Why[4], acc); acc = fmaf(b1v, Why[5], acc);
                acc = fmaf(b2v, Why[6], acc); acc = fmaf(b3v, Why[7], acc);
                out[b] = acc;
            }
        }
    }
}

extern "C" void kernel_launch(void* const* d_in, const int* in_sizes, int n_in,
                              void* d_out, int out_size) {
    const int*   x    = (const int*)d_in[0];
    const float* emb  = (const float*)d_in[1];
    const float* Wxz0 = (const float*)d_in[2];
    const float* Whz0 = (const float*)d_in[3];
    const float* bz0  = (const float*)d_in[4];
    const float* Wxr0 = (const float*)d_in[5];
    const float* Whr0 = (const float*)d_in[6];
    const float* br0  = (const float*)d_in[7];
    const float* WxH0 = (const float*)d_in[8];
    const float* WrH0 = (const float*)d_in[9];
    const float* bH0  = (const float*)d_in[10];
    const float* Wxz  = (const float*)d_in[11];
    const float* Whz  = (const float*)d_in[12];
    const float* bz   = (const float*)d_in[13];
    const float* Wxr  = (const float*)d_in[14];
    const float* Whr  = (const float*)d_in[15];
    const float* br   = (const float*)d_in[16];
    const float* WxH  = (const float*)d_in[17];
    const float* WrH  = (const float*)d_in[18];
    const float* bH   = (const float*)d_in[19];
    const float* Why  = (const float*)d_in[20];
    const float* by   = (const float*)d_in[21];
    float* out = (float*)d_out;

    precompute_xproj<<<(NB * NS + 255) / 256, 256>>>(x, emb, Wxz0, bz0, Wxr0, br0, WxH0, bH0);
    gru_pipeline<<<NL * CS, TPB>>>(Whz0, Whr0, WrH0,
                                   Wxz, Whz, bz, Wxr, Whr, br, WxH, WrH, bH,
                                   Why, by, out, out_size);
}